// round 6
// baseline (speedup 1.0000x reference)
#include <cuda_runtime.h>
#include <cuda_bf16.h>
#include <math.h>
#include <stdint.h>

// Problem dims
#define LL 16
#define TT 2048
#define DD 2048
#define RR 128
#define KCAP 1024
#define WIN 64          // boundary fixup window (ranks KCAP-32 .. KCAP+32)
#define HW (WIN / 2)

// ---------------- scratch (device globals) ----------------
__device__ float g_H[(size_t)LL * TT * RR];
__device__ float g_probs[LL * TT];
__device__ int   g_sel [LL * KCAP];
__device__ int   g_idx0[LL * KCAP];
__device__ int   g_bnd [LL * WIN];
// bf16 split copies, hi/lo interleaved per row: [row][hi: D][lo: D]
__device__ __nv_bfloat16 g_A   [(size_t)LL * TT * 2 * DD];
__device__ __nv_bfloat16 g_Ws1t[(size_t)LL * DD * 2 * DD];   // W_s1^T rows
__device__ __nv_bfloat16 g_Wr1t[(size_t)LL * RR * 2 * DD];   // W_r1^T rows

// ---------------- PTX helpers (baseline ISA only) ----------------
__device__ __forceinline__ uint32_t smem_u32(const void* p) {
    uint32_t a;
    asm("{ .reg .u64 t; cvta.to.shared.u64 t, %1; cvt.u32.u64 %0, t; }" : "=r"(a) : "l"(p));
    return a;
}
#define CP16(dst, src) \
    asm volatile("cp.async.cg.shared.global [%0], [%1], 16;" :: "r"(dst), "l"(src))
#define CP_COMMIT() asm volatile("cp.async.commit_group;")
#define CP_WAIT(n)  asm volatile("cp.async.wait_group %0;" :: "n"(n))

__device__ __forceinline__ void ldsm_x4(uint32_t* r, uint32_t addr) {
    asm volatile("ldmatrix.sync.aligned.m8n8.x4.shared.b16 {%0,%1,%2,%3}, [%4];"
                 : "=r"(r[0]), "=r"(r[1]), "=r"(r[2]), "=r"(r[3]) : "r"(addr));
}
__device__ __forceinline__ void mma16816(float* d, const uint32_t* a,
                                         uint32_t b0, uint32_t b1) {
    asm volatile(
        "mma.sync.aligned.m16n8k16.row.col.f32.bf16.bf16.f32 "
        "{%0,%1,%2,%3}, {%4,%5,%6,%7}, {%8,%9}, {%0,%1,%2,%3};"
        : "+f"(d[0]), "+f"(d[1]), "+f"(d[2]), "+f"(d[3])
        : "r"(a[0]), "r"(a[1]), "r"(a[2]), "r"(a[3]), "r"(b0), "r"(b1));
}

// bf16 hi/lo split of two floats, packed (y<<16)|x
__device__ __forceinline__ void split2(float x, float y, uint32_t& hi, uint32_t& lo) {
    __nv_bfloat16 hx = __float2bfloat16(x);
    __nv_bfloat16 hy = __float2bfloat16(y);
    __nv_bfloat16 lx = __float2bfloat16(x - __bfloat162float(hx));
    __nv_bfloat16 ly = __float2bfloat16(y - __bfloat162float(hy));
    hi = ((uint32_t)__bfloat16_as_ushort(hy) << 16) | __bfloat16_as_ushort(hx);
    lo = ((uint32_t)__bfloat16_as_ushort(ly) << 16) | __bfloat16_as_ushort(lx);
}

// =====================================================================
// hidden f32 -> g_A (hi/lo interleaved per row)
// =====================================================================
__global__ void split_hidden_kernel(const float4* __restrict__ h) {
    size_t i = (size_t)blockIdx.x * blockDim.x + threadIdx.x;   // < L*T*D/4
    float4 v = h[i];
    uint32_t h01, l01, h23, l23;
    split2(v.x, v.y, h01, l01);
    split2(v.z, v.w, h23, l23);
    size_t row = i >> 9;           // DD/4 = 512 float4 per row
    size_t c4  = i & 511;
    uint2* base = (uint2*)(g_A + row * 2 * DD);
    base[c4]       = make_uint2(h01, h23);
    base[c4 + 512] = make_uint2(l01, l23);
}

// =====================================================================
// W[l,k,n] f32 -> Wt[l,n][hi D | lo D] bf16
// =====================================================================
template<bool S1>
__global__ void transpose_split_kernel(const float* __restrict__ W, int K, int N) {
    __shared__ float tile[32][33];
    const int l  = blockIdx.z;
    const int k0 = blockIdx.x * 32;
    const int n0 = blockIdx.y * 32;
    const int tx = threadIdx.x, ty = threadIdx.y;
    const float* Wl = W + (size_t)l * K * N;
    #pragma unroll
    for (int r = 0; r < 4; r++)
        tile[ty + r * 8][tx] = Wl[(size_t)(k0 + ty + r * 8) * N + n0 + tx];
    __syncthreads();
    __nv_bfloat16* Wt = S1 ? g_Ws1t : g_Wr1t;
    #pragma unroll
    for (int r = 0; r < 4; r++) {
        int n = n0 + ty + r * 8;
        float v = tile[tx][ty + r * 8];
        __nv_bfloat16 h = __float2bfloat16(v);
        __nv_bfloat16 lo = __float2bfloat16(v - __bfloat162float(h));
        size_t o = ((size_t)l * N + n) * 2 * DD + k0 + tx;
        Wt[o]      = h;
        Wt[o + DD] = lo;
    }
}

// =====================================================================
// HMMA GEMM, swizzled no-pad SMEM, 3-stage cp.async ring, 1 sync/iter.
// C[128x128] = A @ B^T. NPASS=3: hi/lo split (exact-ish); NPASS=1: hi only.
// SMEM matrix layout: 128 rows x 32 bf16 (64B); granule g (16B) stored at
//   row*64 + (g ^ ((row>>1)&3))*16.   Writer & reader share this formula.
// =====================================================================
#define MAT_B   8192                // 128 rows * 64 B
#define NITER   (DD / 32)           // 64
#define NSTG    3

template<bool GATHER, bool RELU, bool TO_GH, int NPASS>
__global__ __launch_bounds__(256, 2)
void hmma_gemm_kernel(const float* __restrict__ bias,
                      float* __restrict__ Cout, int Ntot) {
    constexpr int NMAT  = (NPASS == 3) ? 4 : 2;     // Ah[,Al],Bh[,Bl]
    constexpr int STG_B = NMAT * MAT_B;
    // matrix offsets in a stage
    constexpr int AH = 0;
    constexpr int AL = (NPASS == 3) ? MAT_B : 0;
    constexpr int BH = (NPASS == 3) ? 2 * MAT_B : MAT_B;
    constexpr int BL = (NPASS == 3) ? 3 * MAT_B : MAT_B;

    extern __shared__ __align__(16) char smraw[];
    const uint32_t smb = smem_u32(smraw);

    const int tid  = threadIdx.x;
    const int lane = tid & 31;
    const int wid  = tid >> 5;
    const int warp_m = wid & 3;     // 4 warps over M (32 rows each)
    const int warp_n = wid >> 2;    // 2 warps over N (64 cols each)
    const int mb = blockIdx.x, nb = blockIdx.y, l = blockIdx.z;

    __shared__ int s_rows[128];
    if (tid < 128)
        s_rows[tid] = GATHER ? g_idx0[l * KCAP + mb * 128 + tid] : (mb * 128 + tid);
    __syncthreads();

    // ---- cp.async ownership: 512 granules (16B) per matrix; 2 per thread
    const int c0 = tid, c1 = tid + 256;
    const int r0 = c0 >> 2, r1 = c1 >> 2;           // row 0..127
    const int g0 = c0 & 3,  g1 = c1 & 3;            // granule 0..3
    const __nv_bfloat16* __restrict__ Aall = g_A + (size_t)l * TT * 2 * DD;
    const __nv_bfloat16* __restrict__ Wt =
        (GATHER ? g_Ws1t : g_Wr1t) + ((size_t)l * Ntot + nb * 128) * 2 * DD;
    const __nv_bfloat16* aPtr0 = Aall + (size_t)s_rows[r0] * 2 * DD + g0 * 8;
    const __nv_bfloat16* aPtr1 = Aall + (size_t)s_rows[r1] * 2 * DD + g1 * 8;
    const __nv_bfloat16* bPtr0 = Wt + (size_t)r0 * 2 * DD + g0 * 8;
    const __nv_bfloat16* bPtr1 = Wt + (size_t)r1 * 2 * DD + g1 * 8;
    const uint32_t d0 = (uint32_t)(r0 * 64 + ((g0 ^ ((r0 >> 1) & 3)) * 16));
    const uint32_t d1 = (uint32_t)(r1 * 64 + ((g1 ^ ((r1 >> 1) & 3)) * 16));

    float acc[2][8][4];
    #pragma unroll
    for (int mt = 0; mt < 2; mt++)
        #pragma unroll
        for (int nt = 0; nt < 8; nt++)
            #pragma unroll
            for (int q = 0; q < 4; q++) acc[mt][nt][q] = 0.0f;

    // ---- ldmatrix addressing (swizzle folds to per-lane constants)
    const uint32_t swz   = (uint32_t)((lane >> 1) & 3);
    const uint32_t gbase = (uint32_t)(lane >> 4);          // 0 or 1
    const uint32_t arow  = (uint32_t)(warp_m * 32 + (lane & 15)) * 64;
    const uint32_t brow  = (uint32_t)(warp_n * 64 + (lane & 15)) * 64;

    auto load_stage = [&](int s, int kt) {
        uint32_t b = smb + s * STG_B;
        CP16(b + AH + d0, aPtr0 + kt);
        CP16(b + BH + d0, bPtr0 + kt);
        CP16(b + AH + d1, aPtr1 + kt);
        CP16(b + BH + d1, bPtr1 + kt);
        if (NPASS == 3) {
            CP16(b + AL + d0, aPtr0 + kt + DD);
            CP16(b + BL + d0, bPtr0 + kt + DD);
            CP16(b + AL + d1, aPtr1 + kt + DD);
            CP16(b + BL + d1, bPtr1 + kt + DD);
        }
    };

    load_stage(0, 0);  CP_COMMIT();
    load_stage(1, 32); CP_COMMIT();

    int st = 0;                 // stage index = c % 3
    for (int c = 0; c < NITER; c++) {
        if (c + 2 < NITER) CP_WAIT(1); else CP_WAIT(0);
        __syncthreads();
        if (c + 2 < NITER) {
            int s2 = st + 2; if (s2 >= NSTG) s2 -= NSTG;
            load_stage(s2, (c + 2) * 32);
            CP_COMMIT();
        }

        const uint32_t sb = smb + st * STG_B;
        #pragma unroll
        for (int ks = 0; ks < 2; ks++) {
            const uint32_t gc = ((gbase + 2 * ks) ^ swz) * 16;
            uint32_t aH[2][4], bfr[4][4];
            #pragma unroll
            for (int mt = 0; mt < 2; mt++)
                ldsm_x4(aH[mt], sb + AH + arow + mt * 1024 + gc);
            #pragma unroll
            for (int n4 = 0; n4 < 4; n4++)
                ldsm_x4(bfr[n4], sb + BH + brow + n4 * 1024 + gc);
            // pass 1: Ah*Bh
            #pragma unroll
            for (int mt = 0; mt < 2; mt++)
                #pragma unroll
                for (int nt = 0; nt < 8; nt++)
                    mma16816(acc[mt][nt], aH[mt], bfr[nt >> 1][nt & 1], bfr[nt >> 1][2 + (nt & 1)]);
            if (NPASS == 3) {
                uint32_t aL[2][4];
                #pragma unroll
                for (int mt = 0; mt < 2; mt++)
                    ldsm_x4(aL[mt], sb + AL + arow + mt * 1024 + gc);
                // pass 2: Al*Bh
                #pragma unroll
                for (int mt = 0; mt < 2; mt++)
                    #pragma unroll
                    for (int nt = 0; nt < 8; nt++)
                        mma16816(acc[mt][nt], aL[mt], bfr[nt >> 1][nt & 1], bfr[nt >> 1][2 + (nt & 1)]);
                // pass 3: Ah*Bl (reuse bfr regs)
                #pragma unroll
                for (int n4 = 0; n4 < 4; n4++)
                    ldsm_x4(bfr[n4], sb + BL + brow + n4 * 1024 + gc);
                #pragma unroll
                for (int mt = 0; mt < 2; mt++)
                    #pragma unroll
                    for (int nt = 0; nt < 8; nt++)
                        mma16816(acc[mt][nt], aH[mt], bfr[nt >> 1][nt & 1], bfr[nt >> 1][2 + (nt & 1)]);
            }
        }
        if (++st >= NSTG) st = 0;
    }

    // ---- epilogue ----
    float* __restrict__ Cbase = TO_GH ? (float*)g_H : Cout;
    const int colb = nb * 128 + warp_n * 64 + (lane & 3) * 2;
    const float* bp = bias + (size_t)l * Ntot + colb;
    #pragma unroll
    for (int mt = 0; mt < 2; mt++) {
        #pragma unroll
        for (int half = 0; half < 2; half++) {
            int rl = warp_m * 32 + mt * 16 + (lane >> 2) + half * 8;
            int grow = s_rows[rl];
            float* dst = Cbase + ((size_t)l * TT + grow) * Ntot + colb;
            #pragma unroll
            for (int nt = 0; nt < 8; nt++) {
                float vx = acc[mt][nt][half * 2 + 0] + bp[nt * 8];
                float vy = acc[mt][nt][half * 2 + 1] + bp[nt * 8 + 1];
                if (RELU) { vx = fmaxf(vx, 0.f); vy = fmaxf(vy, 0.f); }
                *(float2*)(dst + nt * 8) = make_float2(vx, vy);
            }
        }
    }
}

// =====================================================================
// logits + sigmoid (one warp per token, reads g_H)
// =====================================================================
__global__ void logits_kernel(const float* __restrict__ W_r2,
                              const float* __restrict__ b_r2) {
    int gw   = (blockIdx.x * blockDim.x + threadIdx.x) >> 5;
    int lane = threadIdx.x & 31;
    if (gw >= LL * TT) return;
    int l = gw >> 11;
    const float* h = g_H + (size_t)gw * RR;
    const float* w = W_r2 + l * RR;
    float s = 0.0f;
    #pragma unroll
    for (int r = lane; r < RR; r += 32) s += h[r] * w[r];
    #pragma unroll
    for (int o = 16; o; o >>= 1) s += __shfl_xor_sync(0xFFFFFFFFu, s, o);
    if (lane == 0) {
        float x = s + b_r2[l];
        g_probs[gw] = 1.0f / (1.0f + expf(-x));
    }
}

// =====================================================================
// exact rank on (approx) probs -> compaction + boundary window capture
// =====================================================================
__global__ void rank_kernel() {
    __shared__ float sp[TT];
    int l = blockIdx.x;
    for (int t = threadIdx.x; t < TT; t += blockDim.x) sp[t] = g_probs[l * TT + t];
    __syncthreads();
    for (int t = threadIdx.x; t < TT; t += blockDim.x) {
        float pt = sp[t];
        int rank = 0;
        for (int s = 0; s < TT; s++) {
            float ps = sp[s];
            rank += (ps > pt) || (ps == pt && s < t);
        }
        if (rank < KCAP) g_sel[l * KCAP + rank] = t;
        else             g_idx0[l * KCAP + (rank - KCAP)] = t;
        if (rank >= KCAP - HW && rank < KCAP + HW)
            g_bnd[l * WIN + (rank - (KCAP - HW))] = t;
    }
}

// =====================================================================
// exact fp32 recompute of the WIN boundary tokens; re-rank the window.
// one block per layer, 1024 threads (32 warps x 2 tokens)
// =====================================================================
__global__ void fixup_kernel(const float* __restrict__ hidden,
                             const float* __restrict__ W_r1,
                             const float* __restrict__ b_r1,
                             const float* __restrict__ W_r2,
                             const float* __restrict__ b_r2) {
    __shared__ float win_p[WIN];
    __shared__ int   win_t[WIN];
    int l = blockIdx.x, wid = threadIdx.x >> 5, lane = threadIdx.x & 31;
    #pragma unroll
    for (int rep = 0; rep < 2; rep++) {
        int slot = wid + rep * 32;
        int t = g_bnd[l * WIN + slot];
        const float* hrow = hidden + ((size_t)l * TT + t) * DD;
        const float* W1 = W_r1 + (size_t)l * DD * RR;
        float a0 = 0, a1 = 0, a2 = 0, a3 = 0;
        for (int k = 0; k < DD; k++) {
            float hv = hrow[k];
            const float* wr = W1 + (size_t)k * RR + lane;
            a0 = fmaf(hv, wr[0],  a0);
            a1 = fmaf(hv, wr[32], a1);
            a2 = fmaf(hv, wr[64], a2);
            a3 = fmaf(hv, wr[96], a3);
        }
        const float* b1 = b_r1 + l * RR + lane;
        const float* w2 = W_r2 + l * RR + lane;
        float s = fmaxf(a0 + b1[0],  0.f) * w2[0]
                + fmaxf(a1 + b1[32], 0.f) * w2[32]
                + fmaxf(a2 + b1[64], 0.f) * w2[64]
                + fmaxf(a3 + b1[96], 0.f) * w2[96];
        #pragma unroll
        for (int o = 16; o; o >>= 1) s += __shfl_xor_sync(0xFFFFFFFFu, s, o);
        if (lane == 0) {
            float x = s + b_r2[l];
            win_p[slot] = 1.0f / (1.0f + expf(-x));
            win_t[slot] = t;
        }
    }
    __syncthreads();
    if (threadIdx.x < WIN) {
        float pt = win_p[threadIdx.x];
        int   tt = win_t[threadIdx.x];
        int r = 0;
        #pragma unroll
        for (int s2i = 0; s2i < WIN; s2i++) {
            float ps = win_p[s2i];
            int ts = win_t[s2i];
            r += (ps > pt) || (ps == pt && ts < tt);
        }
        if (r < HW) g_sel[l * KCAP + (KCAP - HW) + r] = tt;
        else        g_idx0[l * KCAP + (r - HW)] = tt;
    }
}

// =====================================================================
// selected rows: out = ((1-p)+p) * s2
// =====================================================================
__global__ void copy_sel_kernel(const float* __restrict__ s2,
                                float* __restrict__ out) {
    int b = blockIdx.x;
    int l = b >> 10;
    int t = g_sel[b];
    float p = g_probs[l * TT + t];
    float m = (1.0f - p) + p;
    size_t off = ((size_t)l * TT + t) * DD;
    const float4* src = (const float4*)(s2 + off);
    float4*       dst = (float4*)(out + off);
    #pragma unroll
    for (int i = threadIdx.x; i < DD / 4; i += 256) {
        float4 v = src[i];
        dst[i] = make_float4(m * v.x, m * v.y, m * v.z, m * v.w);
    }
}

// =====================================================================
extern "C" void kernel_launch(void* const* d_in, const int* in_sizes, int n_in,
                              void* d_out, int out_size) {
    const float* hidden = (const float*)d_in[0];
    const float* s2     = (const float*)d_in[1];
    const float* W_r1   = (const float*)d_in[2];
    const float* b_r1   = (const float*)d_in[3];
    const float* W_r2   = (const float*)d_in[4];
    const float* b_r2   = (const float*)d_in[5];
    const float* W_s1   = (const float*)d_in[6];
    const float* b_s1   = (const float*)d_in[7];
    float* out = (float*)d_out;

    const int SMEM_S1 = NSTG * 4 * MAT_B;   // 98304
    const int SMEM_RT = NSTG * 2 * MAT_B;   // 49152
    cudaFuncSetAttribute(hmma_gemm_kernel<true,  false, false, 3>,
                         cudaFuncAttributeMaxDynamicSharedMemorySize, SMEM_S1);
    cudaFuncSetAttribute(hmma_gemm_kernel<false, true,  true,  1>,
                         cudaFuncAttributeMaxDynamicSharedMemorySize, SMEM_RT);

    // precompute bf16 splits
    split_hidden_kernel<<<32768, 512>>>((const float4*)hidden);
    transpose_split_kernel<false><<<dim3(64, 4, 16),  dim3(32, 8)>>>(W_r1, DD, RR);
    transpose_split_kernel<true ><<<dim3(64, 64, 16), dim3(32, 8)>>>(W_s1, DD, DD);

    // router: single-pass bf16 (ranking only; boundary fixed up exactly)
    hmma_gemm_kernel<false, true, true, 1><<<dim3(16, 1, LL), 256, SMEM_RT>>>(
        b_r1, nullptr, RR);
    logits_kernel<<<(LL * TT * 32) / 256, 256>>>(W_r2, b_r2);
    rank_kernel<<<LL, 1024>>>();
    fixup_kernel<<<LL, 1024>>>(hidden, W_r1, b_r1, W_r2, b_r2);
    copy_sel_kernel<<<LL * KCAP, 256>>>(s2, out);

    // s1 GEMM on unselected rows, 3-pass split
    hmma_gemm_kernel<true, false, false, 3><<<dim3(8, 16, LL), 256, SMEM_S1>>>(
        b_s1, out, DD);
}

// round 7
// speedup vs baseline: 1.0777x; 1.0777x over previous
#include <cuda_runtime.h>
#include <cuda_fp16.h>
#include <math.h>
#include <stdint.h>

// Problem dims
#define LL 16
#define TT 2048
#define DD 2048
#define RR 128
#define KCAP 1024
#define WIN 64          // boundary fixup window (ranks KCAP-32 .. KCAP+32)
#define HW (WIN / 2)

// ---------------- scratch (device globals) ----------------
__device__ float g_H[(size_t)LL * TT * RR];
__device__ float g_probs[LL * TT];
__device__ int   g_sel [LL * KCAP];
__device__ int   g_idx0[LL * KCAP];
__device__ int   g_bnd [LL * WIN];
// fp16 copies: A split hi/lo interleaved per row [row][hi: D][lo: D]; W single fp16
__device__ __half g_A   [(size_t)LL * TT * 2 * DD];
__device__ __half g_Ws1t[(size_t)LL * DD * DD];   // W_s1^T [L,N,K]
__device__ __half g_Wr1t[(size_t)LL * RR * DD];   // W_r1^T [L,R,K]

// ---------------- PTX helpers (baseline ISA only) ----------------
__device__ __forceinline__ uint32_t smem_u32(const void* p) {
    uint32_t a;
    asm("{ .reg .u64 t; cvta.to.shared.u64 t, %1; cvt.u32.u64 %0, t; }" : "=r"(a) : "l"(p));
    return a;
}
#define CP16(dst, src) \
    asm volatile("cp.async.cg.shared.global [%0], [%1], 16;" :: "r"(dst), "l"(src))
#define CP_COMMIT() asm volatile("cp.async.commit_group;")
#define CP_WAIT(n)  asm volatile("cp.async.wait_group %0;" :: "n"(n))

__device__ __forceinline__ void ldsm_x4(uint32_t* r, uint32_t addr) {
    asm volatile("ldmatrix.sync.aligned.m8n8.x4.shared.b16 {%0,%1,%2,%3}, [%4];"
                 : "=r"(r[0]), "=r"(r[1]), "=r"(r[2]), "=r"(r[3]) : "r"(addr));
}
__device__ __forceinline__ void mma16816(float* d, const uint32_t* a,
                                         uint32_t b0, uint32_t b1) {
    asm volatile(
        "mma.sync.aligned.m16n8k16.row.col.f32.f16.f16.f32 "
        "{%0,%1,%2,%3}, {%4,%5,%6,%7}, {%8,%9}, {%0,%1,%2,%3};"
        : "+f"(d[0]), "+f"(d[1]), "+f"(d[2]), "+f"(d[3])
        : "r"(a[0]), "r"(a[1]), "r"(a[2]), "r"(a[3]), "r"(b0), "r"(b1));
}

// fp16 hi/lo split of two floats, packed (y<<16)|x
__device__ __forceinline__ void split2(float x, float y, uint32_t& hi, uint32_t& lo) {
    __half hx = __float2half_rn(x);
    __half hy = __float2half_rn(y);
    __half lx = __float2half_rn(x - __half2float(hx));
    __half ly = __float2half_rn(y - __half2float(hy));
    hi = ((uint32_t)__half_as_ushort(hy) << 16) | __half_as_ushort(hx);
    lo = ((uint32_t)__half_as_ushort(ly) << 16) | __half_as_ushort(lx);
}

// =====================================================================
// hidden f32 -> g_A (fp16 hi/lo interleaved per row)
// =====================================================================
__global__ void split_hidden_kernel(const float4* __restrict__ h) {
    size_t i = (size_t)blockIdx.x * blockDim.x + threadIdx.x;   // < L*T*D/4
    float4 v = h[i];
    uint32_t h01, l01, h23, l23;
    split2(v.x, v.y, h01, l01);
    split2(v.z, v.w, h23, l23);
    size_t row = i >> 9;           // DD/4 = 512 float4 per row
    size_t c4  = i & 511;
    uint2* base = (uint2*)(g_A + row * 2 * DD);
    base[c4]       = make_uint2(h01, h23);
    base[c4 + 512] = make_uint2(l01, l23);
}

// =====================================================================
// W[l,k,n] f32 -> Wt[l,n,k] fp16 (round-to-nearest)
// =====================================================================
template<bool S1>
__global__ void transpose_split_kernel(const float* __restrict__ W, int K, int N) {
    __shared__ float tile[32][33];
    const int l  = blockIdx.z;
    const int k0 = blockIdx.x * 32;
    const int n0 = blockIdx.y * 32;
    const int tx = threadIdx.x, ty = threadIdx.y;
    const float* Wl = W + (size_t)l * K * N;
    #pragma unroll
    for (int r = 0; r < 4; r++)
        tile[ty + r * 8][tx] = Wl[(size_t)(k0 + ty + r * 8) * N + n0 + tx];
    __syncthreads();
    __half* Wt = S1 ? g_Ws1t : g_Wr1t;
    #pragma unroll
    for (int r = 0; r < 4; r++) {
        int n = n0 + ty + r * 8;
        float v = tile[tx][ty + r * 8];
        Wt[((size_t)l * N + n) * K + k0 + tx] = __float2half_rn(v);
    }
}

// =====================================================================
// HMMA GEMM (fp16, fp32 accum): C[128x128] = A @ B^T.
//   NPASS=2: (Ah + Al) . Bh   (rel err ~1.4e-4 from B rounding)
//   NPASS=1: Ah . Bh          (router; exact fixup downstream)
// R5-proven structure: PITCH-40 smem, 2-stage cp.async, 2 syncs/iter,
// 256 threads (warps 4x2), 2 CTAs/SM.
// =====================================================================
#define PITCH 40                    // fp16 elts per smem row (32 + 8 pad)
#define MAT_ELT (128 * PITCH)       // 5120 elts per matrix
#define MAT_B   (MAT_ELT * 2)       // 10240 bytes
#define NITER   (DD / 32)           // 64

template<bool GATHER, bool RELU, bool TO_GH, int NPASS>
__global__ __launch_bounds__(256, 2)
void hmma_gemm_kernel(const float* __restrict__ bias,
                      float* __restrict__ Cout, int Ntot) {
    constexpr int NMAT  = NPASS + 1;        // Ah[,Al],B
    constexpr int STG_B = NMAT * MAT_B;
    constexpr int AH = 0;
    constexpr int AL = MAT_B;               // valid only if NPASS==2
    constexpr int BB = NPASS * MAT_B;

    extern __shared__ __align__(16) char smraw[];
    const uint32_t smb = smem_u32(smraw);

    const int tid  = threadIdx.x;
    const int lane = tid & 31;
    const int wid  = tid >> 5;
    const int warp_m = wid & 3;     // 4 warps over M (32 rows each)
    const int warp_n = wid >> 2;    // 2 warps over N (64 cols each)
    const int mb = blockIdx.x, nb = blockIdx.y, l = blockIdx.z;

    __shared__ int s_rows[128];
    if (tid < 128)
        s_rows[tid] = GATHER ? g_idx0[l * KCAP + mb * 128 + tid] : (mb * 128 + tid);
    __syncthreads();

    // cp.async ownership: 512 granules (16B) per matrix; 2 per thread
    const int c0 = tid, c1 = tid + 256;
    const int r0 = c0 >> 2, r1 = c1 >> 2;
    const int f0 = (c0 & 3) * 8, f1 = (c1 & 3) * 8;
    const __half* __restrict__ Aall = g_A + (size_t)l * TT * 2 * DD;
    const __half* __restrict__ Wt =
        (GATHER ? g_Ws1t : g_Wr1t) + ((size_t)l * Ntot + nb * 128) * DD;
    const __half* aPtr0 = Aall + (size_t)s_rows[r0] * 2 * DD + f0;
    const __half* aPtr1 = Aall + (size_t)s_rows[r1] * 2 * DD + f1;
    const __half* bPtr0 = Wt + (size_t)r0 * DD + f0;
    const __half* bPtr1 = Wt + (size_t)r1 * DD + f1;
    const uint32_t d0 = (uint32_t)(r0 * PITCH + f0) * 2;
    const uint32_t d1 = (uint32_t)(r1 * PITCH + f1) * 2;

    float acc[2][8][4];
    #pragma unroll
    for (int mt = 0; mt < 2; mt++)
        #pragma unroll
        for (int nt = 0; nt < 8; nt++)
            #pragma unroll
            for (int q = 0; q < 4; q++) acc[mt][nt][q] = 0.0f;

    // ldmatrix lane addressing (hardware-verified mapping; do not change)
    const uint32_t aoff = (uint32_t)((warp_m * 32 + (lane & 15)) * PITCH + (lane >> 4) * 8) * 2;
    const uint32_t boff = (uint32_t)((warp_n * 64 + (lane & 15)) * PITCH + (lane >> 4) * 8) * 2;

    auto load_stage = [&](int s, int kt) {
        uint32_t b = smb + s * STG_B;
        CP16(b + AH + d0, aPtr0 + kt);
        CP16(b + BB + d0, bPtr0 + kt);
        CP16(b + AH + d1, aPtr1 + kt);
        CP16(b + BB + d1, bPtr1 + kt);
        if (NPASS == 2) {
            CP16(b + AL + d0, aPtr0 + kt + DD);
            CP16(b + AL + d1, aPtr1 + kt + DD);
        }
    };

    load_stage(0, 0);
    CP_COMMIT();

    for (int c = 0; c < NITER; c++) {
        if (c + 1 < NITER) {
            load_stage((c + 1) & 1, (c + 1) * 32);
            CP_COMMIT();
            CP_WAIT(1);
        } else {
            CP_WAIT(0);
        }
        __syncthreads();

        const uint32_t sb = smb + (c & 1) * STG_B;
        #pragma unroll
        for (int ks = 0; ks < 2; ks++) {
            const uint32_t ko = ks * 32;  // 16 elts * 2B
            uint32_t aH[2][4], bfr[4][4];
            #pragma unroll
            for (int mt = 0; mt < 2; mt++)
                ldsm_x4(aH[mt], sb + AH + aoff + mt * (16 * PITCH * 2) + ko);
            #pragma unroll
            for (int n4 = 0; n4 < 4; n4++)
                ldsm_x4(bfr[n4], sb + BB + boff + n4 * (16 * PITCH * 2) + ko);
            // pass 1: Ah*B
            #pragma unroll
            for (int mt = 0; mt < 2; mt++)
                #pragma unroll
                for (int nt = 0; nt < 8; nt++)
                    mma16816(acc[mt][nt], aH[mt], bfr[nt >> 1][nt & 1], bfr[nt >> 1][2 + (nt & 1)]);
            if (NPASS == 2) {
                uint32_t aL[2][4];
                #pragma unroll
                for (int mt = 0; mt < 2; mt++)
                    ldsm_x4(aL[mt], sb + AL + aoff + mt * (16 * PITCH * 2) + ko);
                // pass 2: Al*B (B fragments reused)
                #pragma unroll
                for (int mt = 0; mt < 2; mt++)
                    #pragma unroll
                    for (int nt = 0; nt < 8; nt++)
                        mma16816(acc[mt][nt], aL[mt], bfr[nt >> 1][nt & 1], bfr[nt >> 1][2 + (nt & 1)]);
            }
        }
        __syncthreads();
    }

    // ---- epilogue ----
    float* __restrict__ Cbase = TO_GH ? (float*)g_H : Cout;
    const int colb = nb * 128 + warp_n * 64 + (lane & 3) * 2;
    const float* bp = bias + (size_t)l * Ntot + colb;
    #pragma unroll
    for (int mt = 0; mt < 2; mt++) {
        #pragma unroll
        for (int half = 0; half < 2; half++) {
            int rl = warp_m * 32 + mt * 16 + (lane >> 2) + half * 8;
            int grow = s_rows[rl];
            float* dst = Cbase + ((size_t)l * TT + grow) * Ntot + colb;
            #pragma unroll
            for (int nt = 0; nt < 8; nt++) {
                float vx = acc[mt][nt][half * 2 + 0] + bp[nt * 8];
                float vy = acc[mt][nt][half * 2 + 1] + bp[nt * 8 + 1];
                if (RELU) { vx = fmaxf(vx, 0.f); vy = fmaxf(vy, 0.f); }
                *(float2*)(dst + nt * 8) = make_float2(vx, vy);
            }
        }
    }
}

// =====================================================================
// logits + sigmoid (one warp per token, reads g_H)
// =====================================================================
__global__ void logits_kernel(const float* __restrict__ W_r2,
                              const float* __restrict__ b_r2) {
    int gw   = (blockIdx.x * blockDim.x + threadIdx.x) >> 5;
    int lane = threadIdx.x & 31;
    if (gw >= LL * TT) return;
    int l = gw >> 11;
    const float* h = g_H + (size_t)gw * RR;
    const float* w = W_r2 + l * RR;
    float s = 0.0f;
    #pragma unroll
    for (int r = lane; r < RR; r += 32) s += h[r] * w[r];
    #pragma unroll
    for (int o = 16; o; o >>= 1) s += __shfl_xor_sync(0xFFFFFFFFu, s, o);
    if (lane == 0) {
        float x = s + b_r2[l];
        g_probs[gw] = 1.0f / (1.0f + expf(-x));
    }
}

// =====================================================================
// exact rank on (approx) probs -> compaction + boundary window capture
// =====================================================================
__global__ void rank_kernel() {
    __shared__ float sp[TT];
    int l = blockIdx.x;
    for (int t = threadIdx.x; t < TT; t += blockDim.x) sp[t] = g_probs[l * TT + t];
    __syncthreads();
    for (int t = threadIdx.x; t < TT; t += blockDim.x) {
        float pt = sp[t];
        int rank = 0;
        for (int s = 0; s < TT; s++) {
            float ps = sp[s];
            rank += (ps > pt) || (ps == pt && s < t);
        }
        if (rank < KCAP) g_sel[l * KCAP + rank] = t;
        else             g_idx0[l * KCAP + (rank - KCAP)] = t;
        if (rank >= KCAP - HW && rank < KCAP + HW)
            g_bnd[l * WIN + (rank - (KCAP - HW))] = t;
    }
}

// =====================================================================
// exact fp32 recompute of the WIN boundary tokens; re-rank the window.
// one block per layer, 1024 threads (32 warps x 2 tokens)
// =====================================================================
__global__ void fixup_kernel(const float* __restrict__ hidden,
                             const float* __restrict__ W_r1,
                             const float* __restrict__ b_r1,
                             const float* __restrict__ W_r2,
                             const float* __restrict__ b_r2) {
    __shared__ float win_p[WIN];
    __shared__ int   win_t[WIN];
    int l = blockIdx.x, wid = threadIdx.x >> 5, lane = threadIdx.x & 31;
    #pragma unroll
    for (int rep = 0; rep < 2; rep++) {
        int slot = wid + rep * 32;
        int t = g_bnd[l * WIN + slot];
        const float* hrow = hidden + ((size_t)l * TT + t) * DD;
        const float* W1 = W_r1 + (size_t)l * DD * RR;
        float a0 = 0, a1 = 0, a2 = 0, a3 = 0;
        for (int k = 0; k < DD; k++) {
            float hv = hrow[k];
            const float* wr = W1 + (size_t)k * RR + lane;
            a0 = fmaf(hv, wr[0],  a0);
            a1 = fmaf(hv, wr[32], a1);
            a2 = fmaf(hv, wr[64], a2);
            a3 = fmaf(hv, wr[96], a3);
        }
        const float* b1 = b_r1 + l * RR + lane;
        const float* w2 = W_r2 + l * RR + lane;
        float s = fmaxf(a0 + b1[0],  0.f) * w2[0]
                + fmaxf(a1 + b1[32], 0.f) * w2[32]
                + fmaxf(a2 + b1[64], 0.f) * w2[64]
                + fmaxf(a3 + b1[96], 0.f) * w2[96];
        #pragma unroll
        for (int o = 16; o; o >>= 1) s += __shfl_xor_sync(0xFFFFFFFFu, s, o);
        if (lane == 0) {
            float x = s + b_r2[l];
            win_p[slot] = 1.0f / (1.0f + expf(-x));
            win_t[slot] = t;
        }
    }
    __syncthreads();
    if (threadIdx.x < WIN) {
        float pt = win_p[threadIdx.x];
        int   tt = win_t[threadIdx.x];
        int r = 0;
        #pragma unroll
        for (int s2i = 0; s2i < WIN; s2i++) {
            float ps = win_p[s2i];
            int ts = win_t[s2i];
            r += (ps > pt) || (ps == pt && ts < tt);
        }
        if (r < HW) g_sel[l * KCAP + (KCAP - HW) + r] = tt;
        else        g_idx0[l * KCAP + (r - HW)] = tt;
    }
}

// =====================================================================
// selected rows: out = ((1-p)+p) * s2
// =====================================================================
__global__ void copy_sel_kernel(const float* __restrict__ s2,
                                float* __restrict__ out) {
    int b = blockIdx.x;
    int l = b >> 10;
    int t = g_sel[b];
    float p = g_probs[l * TT + t];
    float m = (1.0f - p) + p;
    size_t off = ((size_t)l * TT + t) * DD;
    const float4* src = (const float4*)(s2 + off);
    float4*       dst = (float4*)(out + off);
    #pragma unroll
    for (int i = threadIdx.x; i < DD / 4; i += 256) {
        float4 v = src[i];
        dst[i] = make_float4(m * v.x, m * v.y, m * v.z, m * v.w);
    }
}

// =====================================================================
extern "C" void kernel_launch(void* const* d_in, const int* in_sizes, int n_in,
                              void* d_out, int out_size) {
    const float* hidden = (const float*)d_in[0];
    const float* s2     = (const float*)d_in[1];
    const float* W_r1   = (const float*)d_in[2];
    const float* b_r1   = (const float*)d_in[3];
    const float* W_r2   = (const float*)d_in[4];
    const float* b_r2   = (const float*)d_in[5];
    const float* W_s1   = (const float*)d_in[6];
    const float* b_s1   = (const float*)d_in[7];
    float* out = (float*)d_out;

    const int SMEM_S1 = 2 * 3 * MAT_B;   // 61440
    const int SMEM_RT = 2 * 2 * MAT_B;   // 40960
    cudaFuncSetAttribute(hmma_gemm_kernel<true,  false, false, 2>,
                         cudaFuncAttributeMaxDynamicSharedMemorySize, SMEM_S1);
    cudaFuncSetAttribute(hmma_gemm_kernel<false, true,  true,  1>,
                         cudaFuncAttributeMaxDynamicSharedMemorySize, SMEM_RT);

    // precompute fp16 splits
    split_hidden_kernel<<<32768, 512>>>((const float4*)hidden);
    transpose_split_kernel<false><<<dim3(64, 4, 16),  dim3(32, 8)>>>(W_r1, DD, RR);
    transpose_split_kernel<true ><<<dim3(64, 64, 16), dim3(32, 8)>>>(W_s1, DD, DD);

    // router: 1-pass fp16 (ranking only; boundary fixed up exactly)
    hmma_gemm_kernel<false, true, true, 1><<<dim3(16, 1, LL), 256, SMEM_RT>>>(
        b_r1, nullptr, RR);
    logits_kernel<<<(LL * TT * 32) / 256, 256>>>(W_r2, b_r2);
    rank_kernel<<<LL, 1024>>>();
    fixup_kernel<<<LL, 1024>>>(hidden, W_r1, b_r1, W_r2, b_r2);
    copy_sel_kernel<<<LL * KCAP, 256>>>(s2, out);

    // s1 GEMM on unselected rows, 2-pass fp16 split
    hmma_gemm_kernel<true, false, false, 2><<<dim3(8, 16, LL), 256, SMEM_S1>>>(
        b_s1, out, DD);
}

// round 8
// speedup vs baseline: 1.2891x; 1.1961x over previous
#include <cuda_runtime.h>
#include <cuda_fp16.h>
#include <math.h>
#include <stdint.h>

// Problem dims
#define LL 16
#define TT 2048
#define DD 2048
#define RR 128
#define KCAP 1024
#define WIN 64          // boundary fixup window (ranks KCAP-32 .. KCAP+32)
#define HW (WIN / 2)

// ---------------- scratch (device globals) ----------------
__device__ float g_H[(size_t)LL * TT * RR];
__device__ float g_probs[LL * TT];
__device__ int   g_sel [LL * KCAP];
__device__ int   g_idx0[LL * KCAP];
__device__ int   g_bnd [LL * WIN];
// fp16 copies (round-to-nearest)
__device__ __half g_A   [(size_t)LL * TT * DD];   // hidden
__device__ __half g_Ws1t[(size_t)LL * DD * DD];   // W_s1^T [L,N,K]
__device__ __half g_Wr1t[(size_t)LL * RR * DD];   // W_r1^T [L,R,K]

// ---------------- PTX helpers (baseline ISA only) ----------------
__device__ __forceinline__ uint32_t smem_u32(const void* p) {
    uint32_t a;
    asm("{ .reg .u64 t; cvta.to.shared.u64 t, %1; cvt.u32.u64 %0, t; }" : "=r"(a) : "l"(p));
    return a;
}
#define CP16(dst, src) \
    asm volatile("cp.async.cg.shared.global [%0], [%1], 16;" :: "r"(dst), "l"(src))
#define CP_COMMIT() asm volatile("cp.async.commit_group;")
#define CP_WAIT(n)  asm volatile("cp.async.wait_group %0;" :: "n"(n))

__device__ __forceinline__ void ldsm_x4(uint32_t* r, uint32_t addr) {
    asm volatile("ldmatrix.sync.aligned.m8n8.x4.shared.b16 {%0,%1,%2,%3}, [%4];"
                 : "=r"(r[0]), "=r"(r[1]), "=r"(r[2]), "=r"(r[3]) : "r"(addr));
}
__device__ __forceinline__ void mma16816(float* d, const uint32_t* a,
                                         uint32_t b0, uint32_t b1) {
    asm volatile(
        "mma.sync.aligned.m16n8k16.row.col.f32.f16.f16.f32 "
        "{%0,%1,%2,%3}, {%4,%5,%6,%7}, {%8,%9}, {%0,%1,%2,%3};"
        : "+f"(d[0]), "+f"(d[1]), "+f"(d[2]), "+f"(d[3])
        : "r"(a[0]), "r"(a[1]), "r"(a[2]), "r"(a[3]), "r"(b0), "r"(b1));
}

// =====================================================================
// hidden f32 -> g_A fp16 (RN)
// =====================================================================
__global__ void split_hidden_kernel(const float4* __restrict__ h) {
    size_t i = (size_t)blockIdx.x * blockDim.x + threadIdx.x;   // < L*T*D/4
    float4 v = h[i];
    __half2 p0 = make_half2(__float2half_rn(v.x), __float2half_rn(v.y));
    __half2 p1 = make_half2(__float2half_rn(v.z), __float2half_rn(v.w));
    ((uint2*)g_A)[i] = make_uint2(*(uint32_t*)&p0, *(uint32_t*)&p1);
}

// =====================================================================
// W[l,k,n] f32 -> Wt[l,n,k] fp16 (RN)
// =====================================================================
template<bool S1>
__global__ void transpose_split_kernel(const float* __restrict__ W, int K, int N) {
    __shared__ float tile[32][33];
    const int l  = blockIdx.z;
    const int k0 = blockIdx.x * 32;
    const int n0 = blockIdx.y * 32;
    const int tx = threadIdx.x, ty = threadIdx.y;
    const float* Wl = W + (size_t)l * K * N;
    #pragma unroll
    for (int r = 0; r < 4; r++)
        tile[ty + r * 8][tx] = Wl[(size_t)(k0 + ty + r * 8) * N + n0 + tx];
    __syncthreads();
    __half* Wt = S1 ? g_Ws1t : g_Wr1t;
    #pragma unroll
    for (int r = 0; r < 4; r++) {
        int n = n0 + ty + r * 8;
        float v = tile[tx][ty + r * 8];
        Wt[((size_t)l * N + n) * K + k0 + tx] = __float2half_rn(v);
    }
}

// =====================================================================
// HMMA GEMM (fp16 single-pass, fp32 accum): C[128x128 tile] = A @ B^T.
// R5-proven structure: PITCH-40 smem, 2-stage cp.async, 2 syncs/iter,
// 256 threads (warps 4x2), 2 CTAs/SM.
// =====================================================================
#define PITCH 40                    // fp16 elts per smem row (32 + 8 pad)
#define MAT_ELT (128 * PITCH)       // 5120 elts per matrix
#define MAT_B   (MAT_ELT * 2)       // 10240 bytes
#define STG_B   (2 * MAT_B)         // A,B : 20480 bytes
#define NITER   (DD / 32)           // 64

template<bool GATHER, bool RELU, bool TO_GH>
__global__ __launch_bounds__(256, 2)
void hmma_gemm_kernel(const float* __restrict__ bias,
                      float* __restrict__ Cout, int Ntot) {
    extern __shared__ __align__(16) char smraw[];
    const uint32_t smb = smem_u32(smraw);

    const int tid  = threadIdx.x;
    const int lane = tid & 31;
    const int wid  = tid >> 5;
    const int warp_m = wid & 3;     // 4 warps over M (32 rows each)
    const int warp_n = wid >> 2;    // 2 warps over N (64 cols each)
    const int mb = blockIdx.x, nb = blockIdx.y, l = blockIdx.z;

    __shared__ int s_rows[128];
    if (tid < 128)
        s_rows[tid] = GATHER ? g_idx0[l * KCAP + mb * 128 + tid] : (mb * 128 + tid);
    __syncthreads();

    // cp.async ownership: 512 granules (16B) per matrix; 2 per thread
    const int c0 = tid, c1 = tid + 256;
    const int r0 = c0 >> 2, r1 = c1 >> 2;
    const int f0 = (c0 & 3) * 8, f1 = (c1 & 3) * 8;
    const __half* __restrict__ Aall = g_A + (size_t)l * TT * DD;
    const __half* __restrict__ Wt =
        (GATHER ? g_Ws1t : g_Wr1t) + ((size_t)l * Ntot + nb * 128) * DD;
    const __half* aPtr0 = Aall + (size_t)s_rows[r0] * DD + f0;
    const __half* aPtr1 = Aall + (size_t)s_rows[r1] * DD + f1;
    const __half* bPtr0 = Wt + (size_t)r0 * DD + f0;
    const __half* bPtr1 = Wt + (size_t)r1 * DD + f1;
    const uint32_t d0 = (uint32_t)(r0 * PITCH + f0) * 2;
    const uint32_t d1 = (uint32_t)(r1 * PITCH + f1) * 2;

    float acc[2][8][4];
    #pragma unroll
    for (int mt = 0; mt < 2; mt++)
        #pragma unroll
        for (int nt = 0; nt < 8; nt++)
            #pragma unroll
            for (int q = 0; q < 4; q++) acc[mt][nt][q] = 0.0f;

    // ldmatrix lane addressing (hardware-verified mapping; do not change)
    const uint32_t aoff = (uint32_t)((warp_m * 32 + (lane & 15)) * PITCH + (lane >> 4) * 8) * 2;
    const uint32_t boff = (uint32_t)((warp_n * 64 + (lane & 15)) * PITCH + (lane >> 4) * 8) * 2;

    auto load_stage = [&](int s, int kt) {
        uint32_t b = smb + s * STG_B;
        CP16(b + d0,         aPtr0 + kt);
        CP16(b + MAT_B + d0, bPtr0 + kt);
        CP16(b + d1,         aPtr1 + kt);
        CP16(b + MAT_B + d1, bPtr1 + kt);
    };

    load_stage(0, 0);
    CP_COMMIT();

    for (int c = 0; c < NITER; c++) {
        if (c + 1 < NITER) {
            load_stage((c + 1) & 1, (c + 1) * 32);
            CP_COMMIT();
            CP_WAIT(1);
        } else {
            CP_WAIT(0);
        }
        __syncthreads();

        const uint32_t sb = smb + (c & 1) * STG_B;
        #pragma unroll
        for (int ks = 0; ks < 2; ks++) {
            const uint32_t ko = ks * 32;  // 16 elts * 2B
            uint32_t aH[2][4], bfr[4][4];
            #pragma unroll
            for (int mt = 0; mt < 2; mt++)
                ldsm_x4(aH[mt], sb + aoff + mt * (16 * PITCH * 2) + ko);
            #pragma unroll
            for (int n4 = 0; n4 < 4; n4++)
                ldsm_x4(bfr[n4], sb + MAT_B + boff + n4 * (16 * PITCH * 2) + ko);
            #pragma unroll
            for (int mt = 0; mt < 2; mt++)
                #pragma unroll
                for (int nt = 0; nt < 8; nt++)
                    mma16816(acc[mt][nt], aH[mt], bfr[nt >> 1][nt & 1], bfr[nt >> 1][2 + (nt & 1)]);
        }
        __syncthreads();
    }

    // ---- epilogue ----
    float* __restrict__ Cbase = TO_GH ? (float*)g_H : Cout;
    const int colb = nb * 128 + warp_n * 64 + (lane & 3) * 2;
    const float* bp = bias + (size_t)l * Ntot + colb;
    #pragma unroll
    for (int mt = 0; mt < 2; mt++) {
        #pragma unroll
        for (int half = 0; half < 2; half++) {
            int rl = warp_m * 32 + mt * 16 + (lane >> 2) + half * 8;
            int grow = s_rows[rl];
            float* dst = Cbase + ((size_t)l * TT + grow) * Ntot + colb;
            #pragma unroll
            for (int nt = 0; nt < 8; nt++) {
                float vx = acc[mt][nt][half * 2 + 0] + bp[nt * 8];
                float vy = acc[mt][nt][half * 2 + 1] + bp[nt * 8 + 1];
                if (RELU) { vx = fmaxf(vx, 0.f); vy = fmaxf(vy, 0.f); }
                *(float2*)(dst + nt * 8) = make_float2(vx, vy);
            }
        }
    }
}

// =====================================================================
// logits + sigmoid (one warp per token, reads g_H)
// =====================================================================
__global__ void logits_kernel(const float* __restrict__ W_r2,
                              const float* __restrict__ b_r2) {
    int gw   = (blockIdx.x * blockDim.x + threadIdx.x) >> 5;
    int lane = threadIdx.x & 31;
    if (gw >= LL * TT) return;
    int l = gw >> 11;
    const float* h = g_H + (size_t)gw * RR;
    const float* w = W_r2 + l * RR;
    float s = 0.0f;
    #pragma unroll
    for (int r = lane; r < RR; r += 32) s += h[r] * w[r];
    #pragma unroll
    for (int o = 16; o; o >>= 1) s += __shfl_xor_sync(0xFFFFFFFFu, s, o);
    if (lane == 0) {
        float x = s + b_r2[l];
        g_probs[gw] = 1.0f / (1.0f + expf(-x));
    }
}

// =====================================================================
// exact rank on (approx) probs -> compaction + boundary window capture
// =====================================================================
__global__ void rank_kernel() {
    __shared__ float sp[TT];
    int l = blockIdx.x;
    for (int t = threadIdx.x; t < TT; t += blockDim.x) sp[t] = g_probs[l * TT + t];
    __syncthreads();
    for (int t = threadIdx.x; t < TT; t += blockDim.x) {
        float pt = sp[t];
        int rank = 0;
        for (int s = 0; s < TT; s++) {
            float ps = sp[s];
            rank += (ps > pt) || (ps == pt && s < t);
        }
        if (rank < KCAP) g_sel[l * KCAP + rank] = t;
        else             g_idx0[l * KCAP + (rank - KCAP)] = t;
        if (rank >= KCAP - HW && rank < KCAP + HW)
            g_bnd[l * WIN + (rank - (KCAP - HW))] = t;
    }
}

// =====================================================================
// exact fp32 recompute of the WIN boundary tokens; re-rank the window.
// one block per layer, 1024 threads (32 warps x 2 tokens)
// =====================================================================
__global__ void fixup_kernel(const float* __restrict__ hidden,
                             const float* __restrict__ W_r1,
                             const float* __restrict__ b_r1,
                             const float* __restrict__ W_r2,
                             const float* __restrict__ b_r2) {
    __shared__ float win_p[WIN];
    __shared__ int   win_t[WIN];
    int l = blockIdx.x, wid = threadIdx.x >> 5, lane = threadIdx.x & 31;
    #pragma unroll
    for (int rep = 0; rep < 2; rep++) {
        int slot = wid + rep * 32;
        int t = g_bnd[l * WIN + slot];
        const float* hrow = hidden + ((size_t)l * TT + t) * DD;
        const float* W1 = W_r1 + (size_t)l * DD * RR;
        float a0 = 0, a1 = 0, a2 = 0, a3 = 0;
        for (int k = 0; k < DD; k++) {
            float hv = hrow[k];
            const float* wr = W1 + (size_t)k * RR + lane;
            a0 = fmaf(hv, wr[0],  a0);
            a1 = fmaf(hv, wr[32], a1);
            a2 = fmaf(hv, wr[64], a2);
            a3 = fmaf(hv, wr[96], a3);
        }
        const float* b1 = b_r1 + l * RR + lane;
        const float* w2 = W_r2 + l * RR + lane;
        float s = fmaxf(a0 + b1[0],  0.f) * w2[0]
                + fmaxf(a1 + b1[32], 0.f) * w2[32]
                + fmaxf(a2 + b1[64], 0.f) * w2[64]
                + fmaxf(a3 + b1[96], 0.f) * w2[96];
        #pragma unroll
        for (int o = 16; o; o >>= 1) s += __shfl_xor_sync(0xFFFFFFFFu, s, o);
        if (lane == 0) {
            float x = s + b_r2[l];
            win_p[slot] = 1.0f / (1.0f + expf(-x));
            win_t[slot] = t;
        }
    }
    __syncthreads();
    if (threadIdx.x < WIN) {
        float pt = win_p[threadIdx.x];
        int   tt = win_t[threadIdx.x];
        int r = 0;
        #pragma unroll
        for (int s2i = 0; s2i < WIN; s2i++) {
            float ps = win_p[s2i];
            int ts = win_t[s2i];
            r += (ps > pt) || (ps == pt && ts < tt);
        }
        if (r < HW) g_sel[l * KCAP + (KCAP - HW) + r] = tt;
        else        g_idx0[l * KCAP + (r - HW)] = tt;
    }
}

// =====================================================================
// selected rows: out = ((1-p)+p) * s2
// =====================================================================
__global__ void copy_sel_kernel(const float* __restrict__ s2,
                                float* __restrict__ out) {
    int b = blockIdx.x;
    int l = b >> 10;
    int t = g_sel[b];
    float p = g_probs[l * TT + t];
    float m = (1.0f - p) + p;
    size_t off = ((size_t)l * TT + t) * DD;
    const float4* src = (const float4*)(s2 + off);
    float4*       dst = (float4*)(out + off);
    #pragma unroll
    for (int i = threadIdx.x; i < DD / 4; i += 256) {
        float4 v = src[i];
        dst[i] = make_float4(m * v.x, m * v.y, m * v.z, m * v.w);
    }
}

// =====================================================================
extern "C" void kernel_launch(void* const* d_in, const int* in_sizes, int n_in,
                              void* d_out, int out_size) {
    const float* hidden = (const float*)d_in[0];
    const float* s2     = (const float*)d_in[1];
    const float* W_r1   = (const float*)d_in[2];
    const float* b_r1   = (const float*)d_in[3];
    const float* W_r2   = (const float*)d_in[4];
    const float* b_r2   = (const float*)d_in[5];
    const float* W_s1   = (const float*)d_in[6];
    const float* b_s1   = (const float*)d_in[7];
    float* out = (float*)d_out;

    const int SMEM = 2 * STG_B;   // 40960
    cudaFuncSetAttribute(hmma_gemm_kernel<true,  false, false>,
                         cudaFuncAttributeMaxDynamicSharedMemorySize, SMEM);
    cudaFuncSetAttribute(hmma_gemm_kernel<false, true,  true>,
                         cudaFuncAttributeMaxDynamicSharedMemorySize, SMEM);

    // precompute fp16 copies
    split_hidden_kernel<<<32768, 512>>>((const float4*)hidden);
    transpose_split_kernel<false><<<dim3(64, 4, 16),  dim3(32, 8)>>>(W_r1, DD, RR);
    transpose_split_kernel<true ><<<dim3(64, 64, 16), dim3(32, 8)>>>(W_s1, DD, DD);

    // router: 1-pass fp16 (ranking only; boundary fixed up exactly)
    hmma_gemm_kernel<false, true, true><<<dim3(16, 1, LL), 256, SMEM>>>(
        b_r1, nullptr, RR);
    logits_kernel<<<(LL * TT * 32) / 256, 256>>>(W_r2, b_r2);
    rank_kernel<<<LL, 1024>>>();
    fixup_kernel<<<LL, 1024>>>(hidden, W_r1, b_r1, W_r2, b_r2);
    copy_sel_kernel<<<LL * KCAP, 256>>>(s2, out);

    // s1 GEMM on unselected rows, single-pass fp16
    hmma_gemm_kernel<true, false, false><<<dim3(8, 16, LL), 256, SMEM>>>(
        b_s1, out, DD);
}

// round 9
// speedup vs baseline: 2.7450x; 2.1295x over previous
#include <cuda_runtime.h>
#include <cuda_fp16.h>
#include <math.h>
#include <stdint.h>

// Problem dims
#define LL 16
#define TT 2048
#define DD 2048
#define RR 128
#define KCAP 1024
#define WIN 64          // boundary fixup window (ranks KCAP-32 .. KCAP+32)
#define HW (WIN / 2)

// ---------------- scratch (device globals) ----------------
__device__ float g_H[(size_t)LL * TT * RR];
__device__ float g_probs[LL * TT];
__device__ int   g_flag[LL * TT];          // 1 = selected (s2 path)
__device__ int   g_sel [LL * KCAP];        // selected tokens, token order
__device__ int   g_idx0[LL * KCAP];        // unselected tokens, token order
__device__ int   g_bnd [LL * WIN];         // boundary tokens (approx-rank order)
__device__ float g_bndp[LL * WIN];         // exact probs for boundary tokens
// fp16 copies (round-to-nearest)
__device__ __half g_A   [(size_t)LL * TT * DD];   // hidden
__device__ __half g_Ws1t[(size_t)LL * DD * DD];   // W_s1^T [L,N,K]
__device__ __half g_Wr1t[(size_t)LL * RR * DD];   // W_r1^T [L,R,K]

// ---------------- PTX helpers (baseline ISA only) ----------------
__device__ __forceinline__ uint32_t smem_u32(const void* p) {
    uint32_t a;
    asm("{ .reg .u64 t; cvta.to.shared.u64 t, %1; cvt.u32.u64 %0, t; }" : "=r"(a) : "l"(p));
    return a;
}
#define CP16(dst, src) \
    asm volatile("cp.async.cg.shared.global [%0], [%1], 16;" :: "r"(dst), "l"(src))
#define CP_COMMIT() asm volatile("cp.async.commit_group;")
#define CP_WAIT(n)  asm volatile("cp.async.wait_group %0;" :: "n"(n))

__device__ __forceinline__ void ldsm_x4(uint32_t* r, uint32_t addr) {
    asm volatile("ldmatrix.sync.aligned.m8n8.x4.shared.b16 {%0,%1,%2,%3}, [%4];"
                 : "=r"(r[0]), "=r"(r[1]), "=r"(r[2]), "=r"(r[3]) : "r"(addr));
}
__device__ __forceinline__ void mma16816(float* d, const uint32_t* a,
                                         uint32_t b0, uint32_t b1) {
    asm volatile(
        "mma.sync.aligned.m16n8k16.row.col.f32.f16.f16.f32 "
        "{%0,%1,%2,%3}, {%4,%5,%6,%7}, {%8,%9}, {%0,%1,%2,%3};"
        : "+f"(d[0]), "+f"(d[1]), "+f"(d[2]), "+f"(d[3])
        : "r"(a[0]), "r"(a[1]), "r"(a[2]), "r"(a[3]), "r"(b0), "r"(b1));
}

// =====================================================================
// hidden f32 -> g_A fp16 (RN)
// =====================================================================
__global__ void split_hidden_kernel(const float4* __restrict__ h) {
    size_t i = (size_t)blockIdx.x * blockDim.x + threadIdx.x;   // < L*T*D/4
    float4 v = h[i];
    __half2 p0 = make_half2(__float2half_rn(v.x), __float2half_rn(v.y));
    __half2 p1 = make_half2(__float2half_rn(v.z), __float2half_rn(v.w));
    ((uint2*)g_A)[i] = make_uint2(*(uint32_t*)&p0, *(uint32_t*)&p1);
}

// =====================================================================
// W[l,k,n] f32 -> Wt[l,n,k] fp16 (RN)
// =====================================================================
template<bool S1>
__global__ void transpose_split_kernel(const float* __restrict__ W, int K, int N) {
    __shared__ float tile[32][33];
    const int l  = blockIdx.z;
    const int k0 = blockIdx.x * 32;
    const int n0 = blockIdx.y * 32;
    const int tx = threadIdx.x, ty = threadIdx.y;
    const float* Wl = W + (size_t)l * K * N;
    #pragma unroll
    for (int r = 0; r < 4; r++)
        tile[ty + r * 8][tx] = Wl[(size_t)(k0 + ty + r * 8) * N + n0 + tx];
    __syncthreads();
    __half* Wt = S1 ? g_Ws1t : g_Wr1t;
    #pragma unroll
    for (int r = 0; r < 4; r++) {
        int n = n0 + ty + r * 8;
        float v = tile[tx][ty + r * 8];
        Wt[((size_t)l * N + n) * K + k0 + tx] = __float2half_rn(v);
    }
}

// =====================================================================
// HMMA GEMM (fp16 single-pass, fp32 accum): C[128x128 tile] = A @ B^T.
// PITCH-40 smem, 2-stage cp.async, 256 threads (warps 4x2), 2 CTAs/SM.
// =====================================================================
#define PITCH 40                    // fp16 elts per smem row (32 + 8 pad)
#define MAT_ELT (128 * PITCH)       // 5120 elts per matrix
#define MAT_B   (MAT_ELT * 2)       // 10240 bytes
#define STG_B   (2 * MAT_B)         // A,B : 20480 bytes
#define NITER   (DD / 32)           // 64

template<bool GATHER, bool RELU, bool TO_GH>
__global__ __launch_bounds__(256, 2)
void hmma_gemm_kernel(const float* __restrict__ bias,
                      float* __restrict__ Cout, int Ntot) {
    extern __shared__ __align__(16) char smraw[];
    const uint32_t smb = smem_u32(smraw);

    const int tid  = threadIdx.x;
    const int lane = tid & 31;
    const int wid  = tid >> 5;
    const int warp_m = wid & 3;
    const int warp_n = wid >> 2;
    const int mb = blockIdx.x, nb = blockIdx.y, l = blockIdx.z;

    __shared__ int s_rows[128];
    if (tid < 128)
        s_rows[tid] = GATHER ? g_idx0[l * KCAP + mb * 128 + tid] : (mb * 128 + tid);
    __syncthreads();

    const int c0 = tid, c1 = tid + 256;
    const int r0 = c0 >> 2, r1 = c1 >> 2;
    const int f0 = (c0 & 3) * 8, f1 = (c1 & 3) * 8;
    const __half* __restrict__ Aall = g_A + (size_t)l * TT * DD;
    const __half* __restrict__ Wt =
        (GATHER ? g_Ws1t : g_Wr1t) + ((size_t)l * Ntot + nb * 128) * DD;
    const __half* aPtr0 = Aall + (size_t)s_rows[r0] * DD + f0;
    const __half* aPtr1 = Aall + (size_t)s_rows[r1] * DD + f1;
    const __half* bPtr0 = Wt + (size_t)r0 * DD + f0;
    const __half* bPtr1 = Wt + (size_t)r1 * DD + f1;
    const uint32_t d0 = (uint32_t)(r0 * PITCH + f0) * 2;
    const uint32_t d1 = (uint32_t)(r1 * PITCH + f1) * 2;

    float acc[2][8][4];
    #pragma unroll
    for (int mt = 0; mt < 2; mt++)
        #pragma unroll
        for (int nt = 0; nt < 8; nt++)
            #pragma unroll
            for (int q = 0; q < 4; q++) acc[mt][nt][q] = 0.0f;

    const uint32_t aoff = (uint32_t)((warp_m * 32 + (lane & 15)) * PITCH + (lane >> 4) * 8) * 2;
    const uint32_t boff = (uint32_t)((warp_n * 64 + (lane & 15)) * PITCH + (lane >> 4) * 8) * 2;

    auto load_stage = [&](int s, int kt) {
        uint32_t b = smb + s * STG_B;
        CP16(b + d0,         aPtr0 + kt);
        CP16(b + MAT_B + d0, bPtr0 + kt);
        CP16(b + d1,         aPtr1 + kt);
        CP16(b + MAT_B + d1, bPtr1 + kt);
    };

    load_stage(0, 0);
    CP_COMMIT();

    for (int c = 0; c < NITER; c++) {
        if (c + 1 < NITER) {
            load_stage((c + 1) & 1, (c + 1) * 32);
            CP_COMMIT();
            CP_WAIT(1);
        } else {
            CP_WAIT(0);
        }
        __syncthreads();

        const uint32_t sb = smb + (c & 1) * STG_B;
        #pragma unroll
        for (int ks = 0; ks < 2; ks++) {
            const uint32_t ko = ks * 32;
            uint32_t aH[2][4], bfr[4][4];
            #pragma unroll
            for (int mt = 0; mt < 2; mt++)
                ldsm_x4(aH[mt], sb + aoff + mt * (16 * PITCH * 2) + ko);
            #pragma unroll
            for (int n4 = 0; n4 < 4; n4++)
                ldsm_x4(bfr[n4], sb + MAT_B + boff + n4 * (16 * PITCH * 2) + ko);
            #pragma unroll
            for (int mt = 0; mt < 2; mt++)
                #pragma unroll
                for (int nt = 0; nt < 8; nt++)
                    mma16816(acc[mt][nt], aH[mt], bfr[nt >> 1][nt & 1], bfr[nt >> 1][2 + (nt & 1)]);
        }
        __syncthreads();
    }

    // ---- epilogue ----
    float* __restrict__ Cbase = TO_GH ? (float*)g_H : Cout;
    const int colb = nb * 128 + warp_n * 64 + (lane & 3) * 2;
    const float* bp = bias + (size_t)l * Ntot + colb;
    #pragma unroll
    for (int mt = 0; mt < 2; mt++) {
        #pragma unroll
        for (int half = 0; half < 2; half++) {
            int rl = warp_m * 32 + mt * 16 + (lane >> 2) + half * 8;
            int grow = s_rows[rl];
            float* dst = Cbase + ((size_t)l * TT + grow) * Ntot + colb;
            #pragma unroll
            for (int nt = 0; nt < 8; nt++) {
                float vx = acc[mt][nt][half * 2 + 0] + bp[nt * 8];
                float vy = acc[mt][nt][half * 2 + 1] + bp[nt * 8 + 1];
                if (RELU) { vx = fmaxf(vx, 0.f); vy = fmaxf(vy, 0.f); }
                *(float2*)(dst + nt * 8) = make_float2(vx, vy);
            }
        }
    }
}

// =====================================================================
// logits + sigmoid (one warp per token, reads g_H)
// =====================================================================
__global__ void logits_kernel(const float* __restrict__ W_r2,
                              const float* __restrict__ b_r2) {
    int gw   = (blockIdx.x * blockDim.x + threadIdx.x) >> 5;
    int lane = threadIdx.x & 31;
    if (gw >= LL * TT) return;
    int l = gw >> 11;
    const float* h = g_H + (size_t)gw * RR;
    const float* w = W_r2 + l * RR;
    float s = 0.0f;
    #pragma unroll
    for (int r = lane; r < RR; r += 32) s += h[r] * w[r];
    #pragma unroll
    for (int o = 16; o; o >>= 1) s += __shfl_xor_sync(0xFFFFFFFFu, s, o);
    if (lane == 0) {
        float x = s + b_r2[l];
        g_probs[gw] = 1.0f / (1.0f + expf(-x));
    }
}

// =====================================================================
// exact rank on (approx) probs -> selected flag + boundary window capture
// =====================================================================
__global__ void rank_kernel() {
    __shared__ float sp[TT];
    int l = blockIdx.x;
    for (int t = threadIdx.x; t < TT; t += blockDim.x) sp[t] = g_probs[l * TT + t];
    __syncthreads();
    for (int t = threadIdx.x; t < TT; t += blockDim.x) {
        float pt = sp[t];
        int rank = 0;
        for (int s = 0; s < TT; s++) {
            float ps = sp[s];
            rank += (ps > pt) || (ps == pt && s < t);
        }
        g_flag[l * TT + t] = (rank < KCAP) ? 1 : 0;
        if (rank >= KCAP - HW && rank < KCAP + HW)
            g_bnd[l * WIN + (rank - (KCAP - HW))] = t;
    }
}

// =====================================================================
// exact fp32 router prob for ONE boundary token per block (fully parallel).
// 256 threads: r = tid & 127, khalf = tid >> 7 covers k in [khalf*1024, +1024)
// =====================================================================
__global__ void fixup_probs_kernel(const float* __restrict__ hidden,
                                   const float* __restrict__ W_r1,
                                   const float* __restrict__ b_r1,
                                   const float* __restrict__ W_r2,
                                   const float* __restrict__ b_r2) {
    __shared__ float sh[DD];          // hidden row
    __shared__ float red[256];
    int b = blockIdx.x;
    int l = b / WIN, slot = b % WIN;
    int t = g_bnd[l * WIN + slot];
    int tid = threadIdx.x;
    const float* hrow = hidden + ((size_t)l * TT + t) * DD;
    for (int k = tid; k < DD; k += 256) sh[k] = hrow[k];
    __syncthreads();

    int r = tid & 127, kh = tid >> 7;
    const float* W1 = W_r1 + (size_t)l * DD * RR + r;
    float a = 0.0f;
    #pragma unroll 4
    for (int k = kh * (DD / 2); k < (kh + 1) * (DD / 2); k++)
        a = fmaf(sh[k], W1[(size_t)k * RR], a);
    red[tid] = a;
    __syncthreads();
    if (tid < 128) {
        float v = red[tid] + red[tid + 128];         // full dot for column r
        v = fmaxf(v + b_r1[l * RR + tid], 0.0f) * W_r2[l * RR + tid];
        red[tid] = v;
    }
    __syncthreads();
    // reduce 128 -> 1
    for (int o = 64; o >= 1; o >>= 1) {
        if (tid < o && o <= 64) red[tid] += red[tid + o];
        __syncthreads();
    }
    if (tid == 0) {
        float x = red[0] + b_r2[l];
        g_bndp[l * WIN + slot] = 1.0f / (1.0f + expf(-x));
    }
}

// =====================================================================
// re-rank the WIN boundary tokens with exact probs; update flags
// =====================================================================
__global__ void fixup_rank_kernel() {
    __shared__ float wp[WIN];
    __shared__ int   wt[WIN];
    int l = blockIdx.x, tid = threadIdx.x;
    if (tid < WIN) { wp[tid] = g_bndp[l * WIN + tid]; wt[tid] = g_bnd[l * WIN + tid]; }
    __syncthreads();
    if (tid < WIN) {
        float pt = wp[tid];
        int tt = wt[tid];
        int r = 0;
        #pragma unroll
        for (int s = 0; s < WIN; s++) {
            float ps = wp[s];
            r += (ps > pt) || (ps == pt && wt[s] < tt);
        }
        g_flag[l * TT + tt] = (r < HW) ? 1 : 0;
    }
}

// =====================================================================
// token-ordered compaction from flags (order within each set is free)
// =====================================================================
__global__ void compact_kernel() {
    __shared__ int fl[TT];
    int l = blockIdx.x;
    for (int t = threadIdx.x; t < TT; t += blockDim.x) fl[t] = g_flag[l * TT + t];
    __syncthreads();
    for (int t = threadIdx.x; t < TT; t += blockDim.x) {
        int before = 0;
        for (int s = 0; s < t; s++) before += fl[s];
        if (fl[t]) g_sel[l * KCAP + before] = t;
        else       g_idx0[l * KCAP + (t - before)] = t;
    }
}

// =====================================================================
// selected rows: out = ((1-p)+p) * s2
// =====================================================================
__global__ void copy_sel_kernel(const float* __restrict__ s2,
                                float* __restrict__ out) {
    int b = blockIdx.x;
    int l = b >> 10;
    int t = g_sel[b];
    float p = g_probs[l * TT + t];
    float m = (1.0f - p) + p;
    size_t off = ((size_t)l * TT + t) * DD;
    const float4* src = (const float4*)(s2 + off);
    float4*       dst = (float4*)(out + off);
    #pragma unroll
    for (int i = threadIdx.x; i < DD / 4; i += 256) {
        float4 v = src[i];
        dst[i] = make_float4(m * v.x, m * v.y, m * v.z, m * v.w);
    }
}

// =====================================================================
extern "C" void kernel_launch(void* const* d_in, const int* in_sizes, int n_in,
                              void* d_out, int out_size) {
    const float* hidden = (const float*)d_in[0];
    const float* s2     = (const float*)d_in[1];
    const float* W_r1   = (const float*)d_in[2];
    const float* b_r1   = (const float*)d_in[3];
    const float* W_r2   = (const float*)d_in[4];
    const float* b_r2   = (const float*)d_in[5];
    const float* W_s1   = (const float*)d_in[6];
    const float* b_s1   = (const float*)d_in[7];
    float* out = (float*)d_out;

    const int SMEM = 2 * STG_B;   // 40960
    cudaFuncSetAttribute(hmma_gemm_kernel<true,  false, false>,
                         cudaFuncAttributeMaxDynamicSharedMemorySize, SMEM);
    cudaFuncSetAttribute(hmma_gemm_kernel<false, true,  true>,
                         cudaFuncAttributeMaxDynamicSharedMemorySize, SMEM);

    // precompute fp16 copies
    split_hidden_kernel<<<32768, 512>>>((const float4*)hidden);
    transpose_split_kernel<false><<<dim3(64, 4, 16),  dim3(32, 8)>>>(W_r1, DD, RR);
    transpose_split_kernel<true ><<<dim3(64, 64, 16), dim3(32, 8)>>>(W_s1, DD, DD);

    // router: 1-pass fp16 (ranking only; boundary fixed up exactly)
    hmma_gemm_kernel<false, true, true><<<dim3(16, 1, LL), 256, SMEM>>>(
        b_r1, nullptr, RR);
    logits_kernel<<<(LL * TT * 32) / 256, 256>>>(W_r2, b_r2);
    rank_kernel<<<LL, 1024>>>();
    fixup_probs_kernel<<<LL * WIN, 256>>>(hidden, W_r1, b_r1, W_r2, b_r2);
    fixup_rank_kernel<<<LL, WIN>>>();
    compact_kernel<<<LL, 1024>>>();
    copy_sel_kernel<<<LL * KCAP, 256>>>(s2, out);

    // s1 GEMM on unselected rows (token-ordered gather)
    hmma_gemm_kernel<true, false, false><<<dim3(8, 16, LL), 256, SMEM>>>(
        b_s1, out, DD);
}